// round 10
// baseline (speedup 1.0000x reference)
#include <cuda_runtime.h>
#include <cuda_bf16.h>

#define B_    8
#define TMAX  256
#define UMAX  128
#define V_    512

#define LOG2E 1.4426950408889634f
#define LN2   0.6931471805599453f
#define NEGF  (-1e30f)

#define DPITCH 400      // diagonal rows per batch (398 touched max)
#define CPITCH 512      // counter rows per batch (aligned)
#define NBLK_LSE 33024  // cells PER BATCH = TMAX*(UMAX+1); one block per cell, 8 warps = 8 batches
#define Z1_END 8385     // cum cells of diags 0..128  (129*130/2)
#define Z2_END 24768    // + 127 diags * 129

// Diagonal-major scratch (log2 domain):
//   g_bd[b][d][u-1] = blank lp at (t,u), d=t+u, u>=1   (pitch 128)
//   g_ed[b][d][u]   = emit  lp at (t,u), d=t+u, u<128  (pitch 128)
//   g_b0[b][t]      = blank lp at (t,0)
__device__ float g_bd[B_ * DPITCH * 128];
__device__ float g_ed[B_ * DPITCH * 128];
__device__ float g_b0[B_ * DPITCH];
__device__ float g_lp[B_];
__device__ int   g_cnt[B_ * CPITCH];      // per-(b,diag) completion counters

__device__ __forceinline__ float ex2f(float x) { float r; asm("ex2.approx.ftz.f32 %0,%1;" : "=f"(r) : "f"(x)); return r; }
__device__ __forceinline__ float lg2f(float x) { float r; asm("lg2.approx.ftz.f32 %0,%1;" : "=f"(r) : "f"(x)); return r; }

__device__ __forceinline__ int4 ld_acq4(const int4* p) {
    int4 v;
    asm volatile("ld.acquire.gpu.global.v4.u32 {%0,%1,%2,%3}, [%4];"
                 : "=r"(v.x), "=r"(v.y), "=r"(v.z), "=r"(v.w) : "l"(p) : "memory");
    return v;
}

// expected #writers for counter row r of a batch with lengths T,U (<=0 => no gate)
__device__ __forceinline__ int expcnt(int r, int T, int U) {
    return min(r, U) - max(0, r - T + 1) + 1;
}

// spin until counter rows r0..r0+7 (16B-aligned r0) are complete
__device__ __forceinline__ void wait8(const int* cb, int r0, int T, int U) {
    const int e0 = expcnt(r0,     T, U), e1 = expcnt(r0 + 1, T, U);
    const int e2 = expcnt(r0 + 2, T, U), e3 = expcnt(r0 + 3, T, U);
    const int e4 = expcnt(r0 + 4, T, U), e5 = expcnt(r0 + 5, T, U);
    const int e6 = expcnt(r0 + 6, T, U), e7 = expcnt(r0 + 7, T, U);
    const int4* p = (const int4*)(cb + r0);
    for (int it = 0; it < (1 << 24); ++it) {      // bounded: deadlock -> wrong result, not timeout
        int4 a = ld_acq4(p);
        int4 b = ld_acq4(p + 1);
        if (a.x >= e0 && a.y >= e1 && a.z >= e2 && a.w >= e3 &&
            b.x >= e4 && b.y >= e5 && b.z >= e6 && b.w >= e7) return;
        __nanosleep(128);
    }
}

// ---------------------------------------------------------------------------
// Init: zero the completion counters (required every graph replay).
// ---------------------------------------------------------------------------
__global__ void init_kernel()
{
    for (int i = threadIdx.x; i < B_ * CPITCH; i += blockDim.x) g_cnt[i] = 0;
}

// ---------------------------------------------------------------------------
// Fused kernel.
//   blocks 0..7         : dp consumer, one warp, batch = blockIdx.x
//   blocks 8..8+33023   : lse producer; block handles cell rem=blockIdx-8 of
//                         ALL 8 batches (warp wid = batch), rem enumerated in
//                         DIAGONAL-MAJOR (t+u ascending) order.
// ---------------------------------------------------------------------------
__global__ __launch_bounds__(256) void fused_kernel(const float* __restrict__ logits,
                                                    const int*   __restrict__ y,
                                                    const int*   __restrict__ T_len,
                                                    const int*   __restrict__ U_len)
{
    if (blockIdx.x < 8) {
        // ================= dp consumer (one warp per batch) =================
        if (threadIdx.x >= 32) return;
        const int b = blockIdx.x;
        const int l = threadIdx.x;
        const int T = T_len[b];
        const int U = U_len[b];
        const int uA = 4 * l + 1;
        const int* cb = g_cnt + b * CPITCH;

        const float4* pb = (const float4*)(g_bd + (size_t)b * DPITCH * 128) + l;
        const float4* pe = (const float4*)(g_ed + (size_t)b * DPITCH * 128) + l;
        const float*  pu = g_b0 + b * DPITCH;

        wait8(cb, 0, T, U);                       // rows 0..7 ready
        float4 sb[8], se[8]; float su[8];
        #pragma unroll
        for (int s = 0; s < 8; ++s) {
            sb[s] = __ldg(pb); pb += 32;
            se[s] = __ldg(pe); pe += 32;
            su[s] = __ldg(pu); pu += 1;
        }

        float cur0 = NEGF, cur1 = NEGF, cur2 = NEGF, cur3 = NEGF;
        float curU0 = 0.f;

        const int dmax  = (T - 1) + U;            // <= 383
        const int dmaxR = ((dmax + 7) >> 3) << 3; // <= 384

#define CELL(CUR, LEFT, BLV, EMV, UU, D)                                  \
        {                                                                 \
            const int  t   = (D) - (UU);                                  \
            const bool act = (t >= 0) && (t < T) && ((UU) <= U);          \
            const float x  = (t == 0) ? NEGF : CUR + (BLV);               \
            const float yv = (LEFT) + (EMV);                              \
            const float mx = fmaxf(x, yv);                                \
            const float mn = fminf(x, yv);                                \
            const float r  = mx + lg2f(1.0f + ex2f(mn - mx));             \
            CUR = act ? r : CUR;                                          \
        }

#define DP_STEP(S, D)                                                     \
        {                                                                 \
            const float4 bv = sb[S];                                      \
            const float4 ev = se[S];                                      \
            const float  uv = su[S];                                      \
            sb[S] = __ldg(pb); pb += 32;                                  \
            se[S] = __ldg(pe); pe += 32;                                  \
            su[S] = __ldg(pu); pu += 1;                                   \
            const float lsh  = __shfl_up_sync(0xffffffffu, cur3, 1);      \
            const float lval = (l == 0) ? curU0 : lsh;                    \
            CELL(cur3, cur2, bv.w, ev.w, uA + 3, D)                       \
            CELL(cur2, cur1, bv.z, ev.z, uA + 2, D)                       \
            CELL(cur1, cur0, bv.y, ev.y, uA + 1, D)                       \
            CELL(cur0, lval, bv.x, ev.x, uA,     D)                       \
            curU0 = ((D) < T) ? curU0 + uv : curU0;                       \
        }

        for (int d = 1; d <= dmaxR; d += 8) {
            wait8(cb, d + 7, T, U);               // rows d+7..d+14 (prefetch targets)
            DP_STEP(0, d)
            DP_STEP(1, d + 1)
            DP_STEP(2, d + 2)
            DP_STEP(3, d + 3)
            DP_STEP(4, d + 4)
            DP_STEP(5, d + 5)
            DP_STEP(6, d + 6)
            DP_STEP(7, d + 7)
        }
#undef DP_STEP
#undef CELL

        const int lo = (U - 1) >> 2;
        const int j  = (U - 1) & 3;
        const float c0 = __shfl_sync(0xffffffffu, cur0, lo);
        const float c1 = __shfl_sync(0xffffffffu, cur1, lo);
        const float c2 = __shfl_sync(0xffffffffu, cur2, lo);
        const float c3 = __shfl_sync(0xffffffffu, cur3, lo);
        const float a  = (j == 0) ? c0 : (j == 1) ? c1 : (j == 2) ? c2 : c3;

        if (l == 0)
            g_lp[b] = a + g_bd[(b * DPITCH + dmax) * 128 + (U - 1)];
        return;
    }

    // ===================== lse producer =====================
    const int rem  = blockIdx.x - 8;              // cell index within a batch, diag-major
    const int b    = threadIdx.x >> 5;            // warp = batch
    const int lane = threadIdx.x & 31;

    // decode rem -> (t,u) with d=t+u ascending
    int t, u;
    if (rem < Z1_END) {                           // diags 0..128, d+1 cells each
        int d = (int)((sqrtf(8.f * rem + 1.f) - 1.f) * 0.5f);
        while ((d + 1) * (d + 2) / 2 <= rem) d++;
        while (d * (d + 1) / 2 > rem) d--;
        u = rem - d * (d + 1) / 2;
        t = d - u;
    } else if (rem < Z2_END) {                    // diags 129..255, 129 cells each
        int idx = rem - Z1_END;
        int d = 129 + idx / 129;
        u = idx % 129;
        t = d - u;
    } else {                                      // diags 256..383, 384-d cells
        int q = (NBLK_LSE - 1) - rem;             // 33023 - rem, in [0, 8255]
        int e = (int)((sqrtf(8.f * q + 1.f) - 1.f) * 0.5f);
        while ((e + 1) * (e + 2) / 2 <= q) e++;
        while (e * (e + 1) / 2 > q) e--;
        int d   = 383 - e;
        int off = q - e * (e + 1) / 2;            // 0..e
        u = 128 - off;                            // u in [d-255, 128]
        t = d - u;
    }

    const int T = T_len[b];
    const int U = U_len[b];
    if (t >= T || u > U) return;                  // inactive: no write, no count

    const int row = (b * TMAX + t) * (UMAX + 1) + u;
    const float* rowp = logits + (size_t)row * V_;
    const float4* p   = (const float4*)rowp;

    float4 r0 = __ldcs(p + lane);
    float4 r1 = __ldcs(p + lane + 32);
    float4 r2 = __ldcs(p + lane + 64);
    float4 r3 = __ldcs(p + lane + 96);

    float s = __expf(r0.x) + __expf(r0.y) + __expf(r0.z) + __expf(r0.w)
            + __expf(r1.x) + __expf(r1.y) + __expf(r1.z) + __expf(r1.w)
            + __expf(r2.x) + __expf(r2.y) + __expf(r2.z) + __expf(r2.w)
            + __expf(r3.x) + __expf(r3.y) + __expf(r3.z) + __expf(r3.w);
    #pragma unroll
    for (int o = 16; o > 0; o >>= 1)
        s += __shfl_xor_sync(0xffffffffu, s, o);

    float lse = __logf(s);

    if (lane == 0) {
        const int d = t + u;
        const float bl = (r0.x - lse) * LOG2E;
        if (u == 0) g_b0[b * DPITCH + t] = bl;
        else        g_bd[(b * DPITCH + d) * 128 + (u - 1)] = bl;
        if (u < UMAX) {
            int yv = y[b * UMAX + u];
            g_ed[(b * DPITCH + d) * 128 + u] = (__ldcs(rowp + yv) - lse) * LOG2E;
        }
        __threadfence();                          // release stores before signal
        atomicAdd(&g_cnt[b * CPITCH + d], 1);
    }
}

// ---------------------------------------------------------------------------
// Finalize: loss = -mean(log_probs), log2 -> natural log.
// ---------------------------------------------------------------------------
__global__ void finalize_kernel(float* __restrict__ out)
{
    float s = (threadIdx.x < B_) ? g_lp[threadIdx.x] : 0.f;
    #pragma unroll
    for (int o = 4; o > 0; o >>= 1)
        s += __shfl_xor_sync(0xffffffffu, s, o);
    if (threadIdx.x == 0) out[0] = -(s * LN2) / (float)B_;
}

extern "C" void kernel_launch(void* const* d_in, const int* in_sizes, int n_in,
                              void* d_out, int out_size)
{
    const float* logits = (const float*)d_in[0];
    const int*   y      = (const int*)  d_in[1];
    const int*   T_len  = (const int*)  d_in[2];
    const int*   U_len  = (const int*)  d_in[3];
    float*       out    = (float*)d_out;

    init_kernel<<<1, 256>>>();
    fused_kernel<<<8 + NBLK_LSE, 256>>>(logits, y, T_len, U_len);
    finalize_kernel<<<1, 32>>>(out);
}

// round 13
// speedup vs baseline: 1.0814x; 1.0814x over previous
#include <cuda_runtime.h>
#include <cuda_bf16.h>

#define B_    8
#define TMAX  256
#define UMAX  128
#define V_    512

#define LOG2E 1.4426950408889634f
#define LN2   0.6931471805599453f
#define NEGF  (-1e30f)

#define DPITCH 400      // stored diagonal rows per batch (<=392 touched)
#define CPITCH 512      // producer-row counters per batch (t in [0,256))
#define NROWS  (B_ * TMAX * (UMAX + 1))   // 264192 producer rows
#define NBLK_P ((NROWS + 7) / 8)          // 33024 producer blocks

// Diagonal-major scratch (log2 domain):
//   g_bd[b][d][u-1] = blank lp at (t,u), d=t+u, u>=1   (pitch 128)
//   g_ed[b][d][u]   = emit  lp at (t,u), d=t+u, u<128  (pitch 128)
//   g_b0[b][t]      = blank lp at (t,0)
__device__ float g_bd[B_ * DPITCH * 128];
__device__ float g_ed[B_ * DPITCH * 128];
__device__ float g_b0[B_ * DPITCH];
__device__ float g_lp[B_];
__device__ int   g_rc[B_ * CPITCH];       // per-(b, producer-row t) counters

__device__ __forceinline__ float ex2f(float x) { float r; asm("ex2.approx.ftz.f32 %0,%1;" : "=f"(r) : "f"(x)); return r; }
__device__ __forceinline__ float lg2f(float x) { float r; asm("lg2.approx.ftz.f32 %0,%1;" : "=f"(r) : "f"(x)); return r; }

__device__ __forceinline__ int4 ld_acq4(const int4* p) {
    int4 v;
    asm volatile("ld.acquire.gpu.global.v4.u32 {%0,%1,%2,%3}, [%4];"
                 : "=r"(v.x), "=r"(v.y), "=r"(v.z), "=r"(v.w) : "l"(p) : "memory");
    return v;
}

// Row t complete when counter == U+1 (rows t>=T are never produced nor needed).
__device__ __forceinline__ int exprow(int r, int T, int U) {
    return (r < T) ? (U + 1) : 0;
}

// Spin until producer rows r0..r0+7 complete (r0 multiple of 8 -> 32B aligned).
__device__ __forceinline__ void wait8(const int* cb, int r0, int T, int U) {
    const int e0 = exprow(r0,     T, U), e1 = exprow(r0 + 1, T, U);
    const int e2 = exprow(r0 + 2, T, U), e3 = exprow(r0 + 3, T, U);
    const int e4 = exprow(r0 + 4, T, U), e5 = exprow(r0 + 5, T, U);
    const int e6 = exprow(r0 + 6, T, U), e7 = exprow(r0 + 7, T, U);
    const int4* p = (const int4*)(cb + r0);
    for (int it = 0; it < (1 << 24); ++it) {      // bounded: bug -> wrong result, not timeout
        int4 a = ld_acq4(p);
        int4 b = ld_acq4(p + 1);
        if (a.x >= e0 && a.y >= e1 && a.z >= e2 && a.w >= e3 &&
            b.x >= e4 && b.y >= e5 && b.z >= e6 && b.w >= e7) return;
        __nanosleep(128);
    }
}

// ---------------------------------------------------------------------------
// Init: zero the row counters (required every graph replay).
// ---------------------------------------------------------------------------
__global__ void init_kernel()
{
    int i = blockIdx.x * 256 + threadIdx.x;
    if (i < B_ * CPITCH) g_rc[i] = 0;
}

// ---------------------------------------------------------------------------
// Fused kernel.
//   blocks 0..7          : dp consumer, one warp, batch = blockIdx.x
//   blocks 8..8+33023    : lse producer, IDENTICAL linear row mapping to the
//                          proven 56us kernel (warp w of block i -> row 8(i-8)+w,
//                          rows enumerated b-major, then t, then u).
// ---------------------------------------------------------------------------
__global__ __launch_bounds__(256) void fused_kernel(const float* __restrict__ logits,
                                                    const int*   __restrict__ y,
                                                    const int*   __restrict__ T_len,
                                                    const int*   __restrict__ U_len)
{
    if (blockIdx.x < 8) {
        // ================= dp consumer (one warp per batch) =================
        if (threadIdx.x >= 32) return;
        const int b = blockIdx.x;
        const int l = threadIdx.x;
        const int T = T_len[b];
        const int U = U_len[b];
        const int uA = 4 * l + 1;
        const int* cb = g_rc + b * CPITCH;

        const float4* pb = (const float4*)(g_bd + (size_t)b * DPITCH * 128) + l;
        const float4* pe = (const float4*)(g_ed + (size_t)b * DPITCH * 128) + l;
        const float*  pu = g_b0 + b * DPITCH;

        wait8(cb, 0, T, U);                       // producer rows 0..7 -> diags 0..7 ready
        float4 sb[8], se[8]; float su[8];
        #pragma unroll
        for (int s = 0; s < 8; ++s) {
            sb[s] = __ldcg(pb); pb += 32;         // L2 (post-acquire safe)
            se[s] = __ldcg(pe); pe += 32;
            su[s] = __ldcg(pu); pu += 1;
        }

        float cur0 = NEGF, cur1 = NEGF, cur2 = NEGF, cur3 = NEGF;
        float curU0 = 0.f;

        const int dmax  = (T - 1) + U;            // <= 383
        const int dmaxR = ((dmax + 7) >> 3) << 3; // <= 384

#define CELL(CUR, LEFT, BLV, EMV, UU, D)                                  \
        {                                                                 \
            const int  t   = (D) - (UU);                                  \
            const bool act = (t >= 0) && (t < T) && ((UU) <= U);          \
            const float x  = (t == 0) ? NEGF : CUR + (BLV);               \
            const float yv = (LEFT) + (EMV);                              \
            const float mx = fmaxf(x, yv);                                \
            const float mn = fminf(x, yv);                                \
            const float r  = mx + lg2f(1.0f + ex2f(mn - mx));             \
            CUR = act ? r : CUR;                                          \
        }

#define DP_STEP(S, D)                                                     \
        {                                                                 \
            const float4 bv = sb[S];                                      \
            const float4 ev = se[S];                                      \
            const float  uv = su[S];                                      \
            sb[S] = __ldcg(pb); pb += 32;                                 \
            se[S] = __ldcg(pe); pe += 32;                                 \
            su[S] = __ldcg(pu); pu += 1;                                  \
            const float lsh  = __shfl_up_sync(0xffffffffu, cur3, 1);      \
            const float lval = (l == 0) ? curU0 : lsh;                    \
            CELL(cur3, cur2, bv.w, ev.w, uA + 3, D)                       \
            CELL(cur2, cur1, bv.z, ev.z, uA + 2, D)                       \
            CELL(cur1, cur0, bv.y, ev.y, uA + 1, D)                       \
            CELL(cur0, lval, bv.x, ev.x, uA,     D)                       \
            curU0 = ((D) < T) ? curU0 + uv : curU0;                       \
        }

        for (int d = 1; d <= dmaxR; d += 8) {
            // Chunk d prefetches stored diag rows d+7..d+14; those need
            // producer rows <= d+14. Prior waits covered rows <= d+6.
            wait8(cb, d + 7, T, U);
            DP_STEP(0, d)
            DP_STEP(1, d + 1)
            DP_STEP(2, d + 2)
            DP_STEP(3, d + 3)
            DP_STEP(4, d + 4)
            DP_STEP(5, d + 5)
            DP_STEP(6, d + 6)
            DP_STEP(7, d + 7)
        }
#undef DP_STEP
#undef CELL

        const int lo = (U - 1) >> 2;
        const int j  = (U - 1) & 3;
        const float c0 = __shfl_sync(0xffffffffu, cur0, lo);
        const float c1 = __shfl_sync(0xffffffffu, cur1, lo);
        const float c2 = __shfl_sync(0xffffffffu, cur2, lo);
        const float c3 = __shfl_sync(0xffffffffu, cur3, lo);
        const float a  = (j == 0) ? c0 : (j == 1) ? c1 : (j == 2) ? c2 : c3;

        if (l == 0)
            g_lp[b] = a + __ldcg(&g_bd[(b * DPITCH + dmax) * 128 + (U - 1)]);
        return;
    }

    // ===================== lse producer (linear row order) =====================
    int row  = (blockIdx.x - 8) * 8 + (threadIdx.x >> 5);
    int lane = threadIdx.x & 31;
    if (row >= NROWS) return;

    int u  = row % (UMAX + 1);
    int bt = row / (UMAX + 1);
    int t  = bt % TMAX;
    int b  = bt / TMAX;

    const int T = T_len[b];
    const int U = U_len[b];
    if (t >= T || u > U) return;                  // inactive: no write, no count

    const float* rowp = logits + (size_t)row * V_;
    const float4* p   = (const float4*)rowp;

    float4 r0 = __ldcs(p + lane);
    float4 r1 = __ldcs(p + lane + 32);
    float4 r2 = __ldcs(p + lane + 64);
    float4 r3 = __ldcs(p + lane + 96);

    float s = __expf(r0.x) + __expf(r0.y) + __expf(r0.z) + __expf(r0.w)
            + __expf(r1.x) + __expf(r1.y) + __expf(r1.z) + __expf(r1.w)
            + __expf(r2.x) + __expf(r2.y) + __expf(r2.z) + __expf(r2.w)
            + __expf(r3.x) + __expf(r3.y) + __expf(r3.z) + __expf(r3.w);
    #pragma unroll
    for (int o = 16; o > 0; o >>= 1)
        s += __shfl_xor_sync(0xffffffffu, s, o);

    float lse = __logf(s);

    if (lane == 0) {
        const int d = t + u;
        const float bl = (r0.x - lse) * LOG2E;
        if (u == 0) g_b0[b * DPITCH + t] = bl;
        else        g_bd[(b * DPITCH + d) * 128 + (u - 1)] = bl;
        if (u < UMAX) {
            int yv = y[b * UMAX + u];
            g_ed[(b * DPITCH + d) * 128 + u] = (__ldcs(rowp + yv) - lse) * LOG2E;
        }
        __threadfence();                          // release stores before signal
        atomicAdd(&g_rc[b * CPITCH + t], 1);      // one signal per (b,t,u) cell
    }
}

// ---------------------------------------------------------------------------
// Finalize: loss = -mean(log_probs), log2 -> natural log.
// ---------------------------------------------------------------------------
__global__ void finalize_kernel(float* __restrict__ out)
{
    float s = (threadIdx.x < B_) ? g_lp[threadIdx.x] : 0.f;
    #pragma unroll
    for (int o = 4; o > 0; o >>= 1)
        s += __shfl_xor_sync(0xffffffffu, s, o);
    if (threadIdx.x == 0) out[0] = -(s * LN2) / (float)B_;
}

extern "C" void kernel_launch(void* const* d_in, const int* in_sizes, int n_in,
                              void* d_out, int out_size)
{
    const float* logits = (const float*)d_in[0];
    const int*   y      = (const int*)  d_in[1];
    const int*   T_len  = (const int*)  d_in[2];
    const int*   U_len  = (const int*)  d_in[3];
    float*       out    = (float*)d_out;

    init_kernel<<<(B_ * CPITCH + 255) / 256, 256>>>();
    fused_kernel<<<8 + NBLK_P, 256>>>(logits, y, T_len, U_len);
    finalize_kernel<<<1, 32>>>(out);
}

// round 14
// speedup vs baseline: 1.2519x; 1.1576x over previous
#include <cuda_runtime.h>
#include <cuda_bf16.h>

#define B_    8
#define TMAX  256
#define UMAX  128
#define V_    512

#define LOG2E 1.4426950408889634f
#define LN2   0.6931471805599453f
#define NEGF  (-1e30f)

#define DPITCH 400      // stored diagonal rows per batch (<=392 touched)
#define CPITCH 512      // producer-row counters per batch (t in [0,256))
#define NROWS  (B_ * TMAX * (UMAX + 1))   // 264192 producer rows
#define NBLK_P ((NROWS + 7) / 8)          // 33024 producer blocks

// Diagonal-major scratch (log2 domain):
//   g_bd[b][d][u-1] = blank lp at (t,u), d=t+u, u>=1   (pitch 128)
//   g_ed[b][d][u]   = emit  lp at (t,u), d=t+u, u<128  (pitch 128)
//   g_b0[b][t]      = blank lp at (t,0)
__device__ float g_bd[B_ * DPITCH * 128];
__device__ float g_ed[B_ * DPITCH * 128];
__device__ float g_b0[B_ * DPITCH];
__device__ float g_lp[B_];
__device__ int   g_rc[B_ * CPITCH];       // per-(b, producer-row t) counters

__device__ __forceinline__ float ex2f(float x) { float r; asm("ex2.approx.ftz.f32 %0,%1;" : "=f"(r) : "f"(x)); return r; }
__device__ __forceinline__ float lg2f(float x) { float r; asm("lg2.approx.ftz.f32 %0,%1;" : "=f"(r) : "f"(x)); return r; }

__device__ __forceinline__ int4 ld_acq4(const int4* p) {
    int4 v;
    asm volatile("ld.acquire.gpu.global.v4.u32 {%0,%1,%2,%3}, [%4];"
                 : "=r"(v.x), "=r"(v.y), "=r"(v.z), "=r"(v.w) : "l"(p) : "memory");
    return v;
}

// Release reduction: orders this thread's prior stores before the increment
// becomes visible, WITHOUT a membar (no CCTL.IVALL L1 flush - the round-13 tax).
__device__ __forceinline__ void red_release_add(int* p, int v) {
    asm volatile("red.release.gpu.global.add.u32 [%0], %1;" :: "l"(p), "r"(v) : "memory");
}

// Row t complete when counter == U+1 (rows t>=T are never produced nor needed).
__device__ __forceinline__ int exprow(int r, int T, int U) {
    return (r < T) ? (U + 1) : 0;
}

// Spin until producer rows r0..r0+7 complete (r0 multiple of 8 -> 32B aligned).
__device__ __forceinline__ void wait8(const int* cb, int r0, int T, int U) {
    const int e0 = exprow(r0,     T, U), e1 = exprow(r0 + 1, T, U);
    const int e2 = exprow(r0 + 2, T, U), e3 = exprow(r0 + 3, T, U);
    const int e4 = exprow(r0 + 4, T, U), e5 = exprow(r0 + 5, T, U);
    const int e6 = exprow(r0 + 6, T, U), e7 = exprow(r0 + 7, T, U);
    const int4* p = (const int4*)(cb + r0);
    for (int it = 0; it < (1 << 24); ++it) {      // bounded: bug -> wrong result, not timeout
        int4 a = ld_acq4(p);
        int4 b = ld_acq4(p + 1);
        if (a.x >= e0 && a.y >= e1 && a.z >= e2 && a.w >= e3 &&
            b.x >= e4 && b.y >= e5 && b.z >= e6 && b.w >= e7) return;
        __nanosleep(128);
    }
}

// ---------------------------------------------------------------------------
// Init: zero the row counters (required every graph replay).
// ---------------------------------------------------------------------------
__global__ void init_kernel()
{
    int i = blockIdx.x * 256 + threadIdx.x;
    if (i < B_ * CPITCH) g_rc[i] = 0;
}

// ---------------------------------------------------------------------------
// Fused kernel.
//   blocks 0..7          : dp consumer, one warp, batch = blockIdx.x
//   blocks 8..8+33023    : lse producer, linear row mapping identical to the
//                          proven 56us kernel (warp w of block i -> row 8(i-8)+w).
// ---------------------------------------------------------------------------
__global__ __launch_bounds__(256) void fused_kernel(const float* __restrict__ logits,
                                                    const int*   __restrict__ y,
                                                    const int*   __restrict__ T_len,
                                                    const int*   __restrict__ U_len)
{
    if (blockIdx.x < 8) {
        // ================= dp consumer (one warp per batch) =================
        if (threadIdx.x >= 32) return;
        const int b = blockIdx.x;
        const int l = threadIdx.x;
        const int T = T_len[b];
        const int U = U_len[b];
        const int uA = 4 * l + 1;
        const int* cb = g_rc + b * CPITCH;

        const float4* pb = (const float4*)(g_bd + (size_t)b * DPITCH * 128) + l;
        const float4* pe = (const float4*)(g_ed + (size_t)b * DPITCH * 128) + l;
        const float*  pu = g_b0 + b * DPITCH;

        wait8(cb, 0, T, U);                       // producer rows 0..7 -> diags 0..7 ready
        float4 sb[8], se[8]; float su[8];
        #pragma unroll
        for (int s = 0; s < 8; ++s) {
            sb[s] = __ldcg(pb); pb += 32;         // L2 (post-acquire safe)
            se[s] = __ldcg(pe); pe += 32;
            su[s] = __ldcg(pu); pu += 1;
        }

        float cur0 = NEGF, cur1 = NEGF, cur2 = NEGF, cur3 = NEGF;
        float curU0 = 0.f;

        const int dmax  = (T - 1) + U;            // <= 383
        const int dmaxR = ((dmax + 7) >> 3) << 3; // <= 384

#define CELL(CUR, LEFT, BLV, EMV, UU, D)                                  \
        {                                                                 \
            const int  t   = (D) - (UU);                                  \
            const bool act = (t >= 0) && (t < T) && ((UU) <= U);          \
            const float x  = (t == 0) ? NEGF : CUR + (BLV);               \
            const float yv = (LEFT) + (EMV);                              \
            const float mx = fmaxf(x, yv);                                \
            const float mn = fminf(x, yv);                                \
            const float r  = mx + lg2f(1.0f + ex2f(mn - mx));             \
            CUR = act ? r : CUR;                                          \
        }

#define DP_STEP(S, D)                                                     \
        {                                                                 \
            const float4 bv = sb[S];                                      \
            const float4 ev = se[S];                                      \
            const float  uv = su[S];                                      \
            sb[S] = __ldcg(pb); pb += 32;                                 \
            se[S] = __ldcg(pe); pe += 32;                                 \
            su[S] = __ldcg(pu); pu += 1;                                  \
            const float lsh  = __shfl_up_sync(0xffffffffu, cur3, 1);      \
            const float lval = (l == 0) ? curU0 : lsh;                    \
            CELL(cur3, cur2, bv.w, ev.w, uA + 3, D)                       \
            CELL(cur2, cur1, bv.z, ev.z, uA + 2, D)                       \
            CELL(cur1, cur0, bv.y, ev.y, uA + 1, D)                       \
            CELL(cur0, lval, bv.x, ev.x, uA,     D)                       \
            curU0 = ((D) < T) ? curU0 + uv : curU0;                       \
        }

        for (int d = 1; d <= dmaxR; d += 8) {
            // Chunk d prefetches stored diag rows d+7..d+14; those need
            // producer rows <= d+14. Prior waits covered rows <= d+6.
            wait8(cb, d + 7, T, U);
            DP_STEP(0, d)
            DP_STEP(1, d + 1)
            DP_STEP(2, d + 2)
            DP_STEP(3, d + 3)
            DP_STEP(4, d + 4)
            DP_STEP(5, d + 5)
            DP_STEP(6, d + 6)
            DP_STEP(7, d + 7)
        }
#undef DP_STEP
#undef CELL

        const int lo = (U - 1) >> 2;
        const int j  = (U - 1) & 3;
        const float c0 = __shfl_sync(0xffffffffu, cur0, lo);
        const float c1 = __shfl_sync(0xffffffffu, cur1, lo);
        const float c2 = __shfl_sync(0xffffffffu, cur2, lo);
        const float c3 = __shfl_sync(0xffffffffu, cur3, lo);
        const float a  = (j == 0) ? c0 : (j == 1) ? c1 : (j == 2) ? c2 : c3;

        if (l == 0)
            g_lp[b] = a + __ldcg(&g_bd[(b * DPITCH + dmax) * 128 + (U - 1)]);
        return;
    }

    // ===================== lse producer (linear row order) =====================
    int row  = (blockIdx.x - 8) * 8 + (threadIdx.x >> 5);
    int lane = threadIdx.x & 31;
    if (row >= NROWS) return;

    int u  = row % (UMAX + 1);
    int bt = row / (UMAX + 1);
    int t  = bt % TMAX;
    int b  = bt / TMAX;

    const int T = T_len[b];
    const int U = U_len[b];
    if (t >= T || u > U) return;                  // inactive: no write, no count

    const float* rowp = logits + (size_t)row * V_;
    const float4* p   = (const float4*)rowp;

    float4 r0 = __ldcs(p + lane);
    float4 r1 = __ldcs(p + lane + 32);
    float4 r2 = __ldcs(p + lane + 64);
    float4 r3 = __ldcs(p + lane + 96);

    float s = __expf(r0.x) + __expf(r0.y) + __expf(r0.z) + __expf(r0.w)
            + __expf(r1.x) + __expf(r1.y) + __expf(r1.z) + __expf(r1.w)
            + __expf(r2.x) + __expf(r2.y) + __expf(r2.z) + __expf(r2.w)
            + __expf(r3.x) + __expf(r3.y) + __expf(r3.z) + __expf(r3.w);
    #pragma unroll
    for (int o = 16; o > 0; o >>= 1)
        s += __shfl_xor_sync(0xffffffffu, s, o);

    float lse = __logf(s);

    if (lane == 0) {
        const int d = t + u;
        const float bl = (r0.x - lse) * LOG2E;
        if (u == 0) g_b0[b * DPITCH + t] = bl;
        else        g_bd[(b * DPITCH + d) * 128 + (u - 1)] = bl;
        if (u < UMAX) {
            int yv = y[b * UMAX + u];
            g_ed[(b * DPITCH + d) * 128 + u] = (__ldcs(rowp + yv) - lse) * LOG2E;
        }
        red_release_add(&g_rc[b * CPITCH + t], 1);   // release-ordered signal, no membar
    }
}

// ---------------------------------------------------------------------------
// Finalize: loss = -mean(log_probs), log2 -> natural log.
// ---------------------------------------------------------------------------
__global__ void finalize_kernel(float* __restrict__ out)
{
    float s = (threadIdx.x < B_) ? g_lp[threadIdx.x] : 0.f;
    #pragma unroll
    for (int o = 4; o > 0; o >>= 1)
        s += __shfl_xor_sync(0xffffffffu, s, o);
    if (threadIdx.x == 0) out[0] = -(s * LN2) / (float)B_;
}

extern "C" void kernel_launch(void* const* d_in, const int* in_sizes, int n_in,
                              void* d_out, int out_size)
{
    const float* logits = (const float*)d_in[0];
    const int*   y      = (const int*)  d_in[1];
    const int*   T_len  = (const int*)  d_in[2];
    const int*   U_len  = (const int*)  d_in[3];
    float*       out    = (float*)d_out;

    init_kernel<<<(B_ * CPITCH + 255) / 256, 256>>>();
    fused_kernel<<<8 + NBLK_P, 256>>>(logits, y, T_len, U_len);
    finalize_kernel<<<1, 32>>>(out);
}